// round 9
// baseline (speedup 1.0000x reference)
#include <cuda_runtime.h>
#include <cstdint>

// ============================================================================
// LinearDeepSeekV3: y = act_quant(x) @ dequant(weight)^T
// M=16384, N=256, K=7168, fp8 e4m3 weight with [128x128] block scales.
// Baseline-ISA (plain sm_103): legacy mma.sync.m16n8k32.e4m3, fp32 accum,
// per-k-block scale fold (exact reference reassociation).
//
// R8: WARP SPECIALIZATION. 8 consumer warps (MMA only) + 4 producer warps
// (x LDG -> quant -> STS A, cp.async B) over a 4-stage SMEM ring, synced with
// named barriers (full: id 8+s, empty: id 12+s, total count 384). Producers
// run ahead; the tensor pipe never waits on quant or loads. 1 CTA/SM.
// ============================================================================

#define KDIM 7168
#define NDIM 256
#define KC 128
#define KB 56
#define MT 64
#define NTH 384
#define NCONS 256

// ---- shared memory layout (bytes), 4 stages ----
#define OFF_BS 0            // [4][256][128] u8 = 131072 (swizzled)
#define OFF_AS 131072       // [4][64][128] u8 = 32768 (swizzled)
#define OFF_SC 163840       // [4][64] f32 = 1024
#define OFF_WS 164864       // [112] f32 = 448
#define SMEM_TOTAL 165376

__device__ __align__(16) uint8_t g_w8[(size_t)NDIM * KDIM];

__device__ __forceinline__ uint32_t smem_u32(const void* p) {
    uint32_t a;
    asm("{ .reg .u64 t; cvta.to.shared.u64 t, %1; cvt.u32.u64 %0, t; }" : "=r"(a) : "l"(p));
    return a;
}

#define CP_ASYNC16(dst, src) \
    asm volatile("cp.async.cg.shared.global [%0], [%1], 16;" :: "r"(dst), "l"(src) : "memory")

#define BAR_SYNC(id) \
    asm volatile("bar.sync %0, %1;" :: "r"(id), "r"(NTH) : "memory")
#define BAR_ARRIVE(id) \
    asm volatile("bar.arrive %0, %1;" :: "r"(id), "r"(NTH) : "memory")

#define LDMATRIX_X4(r0, r1, r2, r3, addr) \
    asm volatile("ldmatrix.sync.aligned.m8n8.x4.shared.b16 {%0,%1,%2,%3}, [%4];" \
        : "=r"(r0), "=r"(r1), "=r"(r2), "=r"(r3) : "r"(addr))

#define MMA_E4M3(d0, d1, d2, d3, a0, a1, a2, a3, b0, b1) \
    asm volatile("mma.sync.aligned.m16n8k32.row.col.f32.e4m3.e4m3.f32 " \
        "{%0,%1,%2,%3}, {%4,%5,%6,%7}, {%8,%9}, {%0,%1,%2,%3};" \
        : "+f"(d0), "+f"(d1), "+f"(d2), "+f"(d3) \
        : "r"(a0), "r"(a1), "r"(a2), "r"(a3), "r"(b0), "r"(b1))

#define MMA_E4M3_ZC(d0, d1, d2, d3, a0, a1, a2, a3, b0, b1, z) \
    asm volatile("mma.sync.aligned.m16n8k32.row.col.f32.e4m3.e4m3.f32 " \
        "{%0,%1,%2,%3}, {%4,%5,%6,%7}, {%8,%9}, {%10,%10,%10,%10};" \
        : "=f"(d0), "=f"(d1), "=f"(d2), "=f"(d3) \
        : "r"(a0), "r"(a1), "r"(a2), "r"(a3), "r"(b0), "r"(b1), "f"(z))

// ============================================================================
// Weight canonicalization (harness upcasts fp8 inputs to f32; detect + cvt).
// Deterministic: every block tests the SAME first 4096 elements.
// ============================================================================
__global__ void conv_kernel(const void* w) {
    __shared__ int cnt;
    const int tid = threadIdx.x;
    if (tid == 0) cnt = 0;
    __syncthreads();
    const float* wf = (const float*)w;
    int ok = 0;
#pragma unroll
    for (int i = 0; i < 16; ++i) {
        float v = wf[tid + i * 256];
        if (isfinite(v) && fabsf(v) <= 1.0f) ok++;
    }
#pragma unroll
    for (int o = 16; o; o >>= 1) ok += __shfl_xor_sync(0xffffffffu, ok, o);
    if ((tid & 31) == 0) atomicAdd(&cnt, ok);
    __syncthreads();
    const bool is_f32 = (cnt >= 4000);

    const int i4 = blockIdx.x * 256 + tid;
    constexpr int TOT4 = NDIM * KDIM / 4;
    if (i4 >= TOT4) return;
    uint32_t outw;
    if (is_f32) {
        const float4 v = ((const float4*)w)[i4];
        unsigned short lo, hi;
        asm("cvt.rn.satfinite.e4m3x2.f32 %0, %1, %2;" : "=h"(lo) : "f"(v.y), "f"(v.x));
        asm("cvt.rn.satfinite.e4m3x2.f32 %0, %1, %2;" : "=h"(hi) : "f"(v.w), "f"(v.z));
        outw = (uint32_t)lo | ((uint32_t)hi << 16);
    } else {
        outw = ((const uint32_t*)w)[i4];
    }
    ((uint32_t*)g_w8)[i4] = outw;
}

// ============================================================================
// Warp-specialized fused GEMM
// ============================================================================
__global__ void __launch_bounds__(NTH, 1)
fused_fp8_gemm(const float* __restrict__ x, const float* __restrict__ ws,
               float* __restrict__ out) {
    extern __shared__ char smem[];
    const uint32_t sb = smem_u32(smem);
    const int tid = threadIdx.x;
    const int lane = tid & 31;
    const int wid = tid >> 5;
    const size_t m0cta = (size_t)blockIdx.x * MT;

    if (tid < 112) ((float*)(smem + OFF_WS))[tid] = ws[tid];
    __syncthreads();

    float* SCm = (float*)(smem + OFF_SC);
    const float* WS = (const float*)(smem + OFF_WS);

    if (wid >= 8) {
        // ==================== PRODUCER (4 warps, 128 threads) ====================
        const int ptid = tid - NCONS;
        const int qrow = ptid >> 1;            // 0..63
        const int qq = ptid & 1;               // half of the 128-col chunk
        const int qsw = qrow & 7;
        const float4* xr = (const float4*)(x + (m0cta + qrow) * KDIM);
        const int bu = ptid & 7;               // 16B unit within B row
        const int bn0 = ptid >> 3;             // 0..15

#pragma unroll 1
        for (int kc = 0; kc < KB; ++kc) {
            const int s = kc & 3;
            if (kc >= 4) BAR_SYNC(12 + s);

            // ---- B tile: 256x128 fp8 via cp.async (swizzled) ----
            const uint32_t bbase = sb + OFF_BS + s * 32768;
            const uint8_t* bsrc = g_w8 + (size_t)kc * KC + bu * 16;
#pragma unroll
            for (int i = 0; i < 16; ++i) {
                const int n = bn0 + i * 16;
                CP_ASYNC16(bbase + n * 128 + ((bu ^ (n & 7)) * 16),
                           bsrc + (size_t)n * KDIM);
            }
            asm volatile("cp.async.commit_group;" ::: "memory");

            // ---- act-quant: 2 threads/row, 64 values each (exact ref numerics) ----
            float4 v[16];
#pragma unroll
            for (int i = 0; i < 16; ++i) v[i] = xr[kc * 32 + qq * 16 + i];
            float am = 0.f;
#pragma unroll
            for (int i = 0; i < 16; ++i)
                am = fmaxf(am, fmaxf(fmaxf(fabsf(v[i].x), fabsf(v[i].y)),
                                     fmaxf(fabsf(v[i].z), fabsf(v[i].w))));
            am = fmaxf(am, __shfl_xor_sync(0xffffffffu, am, 1));
            const float amax = fmaxf(am, 1e-8f);
            const float sc = __fdiv_rn(amax, 448.0f);
            const float ri = __fdiv_rn(448.0f, amax);
            uint32_t wd[16];
#pragma unroll
            for (int i = 0; i < 16; ++i) {
                unsigned short lo, hi;
                asm("cvt.rn.satfinite.e4m3x2.f32 %0, %1, %2;"
                    : "=h"(lo) : "f"(v[i].y * ri), "f"(v[i].x * ri));
                asm("cvt.rn.satfinite.e4m3x2.f32 %0, %1, %2;"
                    : "=h"(hi) : "f"(v[i].w * ri), "f"(v[i].z * ri));
                wd[i] = (uint32_t)lo | ((uint32_t)hi << 16);
            }

            asm volatile("cp.async.wait_group 0;" ::: "memory");

            const uint32_t abase = sb + OFF_AS + s * 8192 + qrow * 128;
#pragma unroll
            for (int j = 0; j < 4; ++j) {
                const uint32_t u = (uint32_t)((qq * 4 + j) ^ qsw);
                asm volatile("st.shared.v4.b32 [%0], {%1,%2,%3,%4};"
                    :: "r"(abase + u * 16),
                       "r"(wd[4*j]), "r"(wd[4*j+1]), "r"(wd[4*j+2]), "r"(wd[4*j+3])
                    : "memory");
            }
            if (qq == 0) SCm[s * 64 + qrow] = sc;

            BAR_ARRIVE(8 + s);
        }
    } else {
        // ==================== CONSUMER (8 warps, 256 threads) ====================
        // warp grid 2m x 4n, warp tile m32 x n64
        const int R0 = (wid >> 2) * 32;
        const int C0 = (wid & 3) * 64;
        const int nb = (wid & 3) >> 1;
        const int alane = lane & 15, asel = lane >> 4;
        const int nlane = (lane & 7) | ((lane >> 4) << 3);
        const int bsel = (lane >> 3) & 1;
        const int lr = lane >> 2;

        float acc[64];
#pragma unroll
        for (int i = 0; i < 64; ++i) acc[i] = 0.f;

#pragma unroll 1
        for (int kc = 0; kc < KB; ++kc) {
            const int s = kc & 3;
            BAR_SYNC(8 + s);

            const uint32_t ab = sb + OFF_AS + s * 8192;
            const uint32_t bb = sb + OFF_BS + s * 32768;
            const float wv = WS[nb * 56 + kc];
            float f[4];
#pragma unroll
            for (int mh = 0; mh < 2; ++mh) {
                f[mh * 2 + 0] = SCm[s * 64 + R0 + mh * 16 + lr] * wv;
                f[mh * 2 + 1] = SCm[s * 64 + R0 + mh * 16 + 8 + lr] * wv;
            }

            // preload all A fragments for this chunk (4 ks x 2 mh)
            uint32_t a[4][2][4];
#pragma unroll
            for (int ks = 0; ks < 4; ++ks) {
#pragma unroll
                for (int mh = 0; mh < 2; ++mh) {
                    const int r = R0 + mh * 16 + alane;
                    const uint32_t ad = ab + r * 128 + (((ks * 2 + asel) ^ (r & 7)) * 16);
                    LDMATRIX_X4(a[ks][mh][0], a[ks][mh][1], a[ks][mh][2], a[ks][mh][3], ad);
                }
            }

#pragma unroll
            for (int ng = 0; ng < 4; ++ng) {
                float p[16];
                const int nr = C0 + ng * 16 + nlane;
                // ks = 0: init partials through zero C operand
                {
                    const uint32_t bd = bb + nr * 128 + ((bsel ^ (nr & 7)) * 16);
                    uint32_t b0, b1, b2, b3;
                    LDMATRIX_X4(b0, b1, b2, b3, bd);
#pragma unroll
                    for (int mh = 0; mh < 2; ++mh) {
                        MMA_E4M3_ZC(p[mh*8+0], p[mh*8+1], p[mh*8+2], p[mh*8+3],
                                    a[0][mh][0], a[0][mh][1], a[0][mh][2], a[0][mh][3],
                                    b0, b1, 0.f);
                        MMA_E4M3_ZC(p[mh*8+4], p[mh*8+5], p[mh*8+6], p[mh*8+7],
                                    a[0][mh][0], a[0][mh][1], a[0][mh][2], a[0][mh][3],
                                    b2, b3, 0.f);
                    }
                }
#pragma unroll
                for (int ks = 1; ks < 4; ++ks) {
                    const uint32_t bd = bb + nr * 128 + (((ks * 2 + bsel) ^ (nr & 7)) * 16);
                    uint32_t b0, b1, b2, b3;
                    LDMATRIX_X4(b0, b1, b2, b3, bd);
#pragma unroll
                    for (int mh = 0; mh < 2; ++mh) {
                        MMA_E4M3(p[mh*8+0], p[mh*8+1], p[mh*8+2], p[mh*8+3],
                                 a[ks][mh][0], a[ks][mh][1], a[ks][mh][2], a[ks][mh][3],
                                 b0, b1);
                        MMA_E4M3(p[mh*8+4], p[mh*8+5], p[mh*8+6], p[mh*8+7],
                                 a[ks][mh][0], a[ks][mh][1], a[ks][mh][2], a[ks][mh][3],
                                 b2, b3);
                    }
                }
                // fold scales once per chunk
#pragma unroll
                for (int mh = 0; mh < 2; ++mh) {
#pragma unroll
                    for (int pr = 0; pr < 2; ++pr) {
                        const int pi = mh * 8 + pr * 4;
                        const int ai = ng * 16 + pi;
                        acc[ai+0] = fmaf(p[pi+0], f[mh*2+0], acc[ai+0]);
                        acc[ai+1] = fmaf(p[pi+1], f[mh*2+0], acc[ai+1]);
                        acc[ai+2] = fmaf(p[pi+2], f[mh*2+1], acc[ai+2]);
                        acc[ai+3] = fmaf(p[pi+3], f[mh*2+1], acc[ai+3]);
                    }
                }
            }
            BAR_ARRIVE(12 + s);
        }

        // ================= epilogue (consumers only) =================
#pragma unroll
        for (int mh = 0; mh < 2; ++mh) {
            const int row = R0 + mh * 16 + lr;
            float* o0 = out + (m0cta + row) * NDIM;
#pragma unroll
            for (int ng = 0; ng < 4; ++ng) {
#pragma unroll
                for (int pr = 0; pr < 2; ++pr) {
                    const int base = ng * 16 + mh * 8 + pr * 4;
                    const int col = C0 + ng * 16 + pr * 8 + (lane & 3) * 2;
                    *(float2*)(o0 + col) = make_float2(acc[base], acc[base+1]);
                    *(float2*)(o0 + 8 * NDIM + col) = make_float2(acc[base+2], acc[base+3]);
                }
            }
        }
    }
}

// ============================================================================
extern "C" void kernel_launch(void* const* d_in, const int* in_sizes, int n_in,
                              void* d_out, int out_size) {
    const float* x = (const float*)d_in[0];
    const void* w = d_in[1];
    const float* ws = (const float*)d_in[2];
    float* out = (float*)d_out;

    const int M = in_sizes[0] / KDIM;       // 16384
    const int grid = M / MT;                // 256

    cudaFuncSetAttribute(fused_fp8_gemm, cudaFuncAttributeMaxDynamicSharedMemorySize, SMEM_TOTAL);

    conv_kernel<<<(NDIM * KDIM / 4 + 255) / 256, 256>>>(w);
    fused_fp8_gemm<<<grid, NTH, SMEM_TOTAL>>>(x, ws, out);
}

// round 11
// speedup vs baseline: 1.2128x; 1.2128x over previous
#include <cuda_runtime.h>
#include <cstdint>

// ============================================================================
// LinearDeepSeekV3: y = act_quant(x) @ dequant(weight)^T
// M=16384, N=256, K=7168, fp8 e4m3 weight with [128x128] block scales.
// Baseline-ISA (plain sm_103): legacy mma.sync.m16n8k32.e4m3, fp32 accum.
//
// R9 = R6 config (separate quant kernel; GEMM 2 CTAs/SM, pre-quantized A)
//      + B-fragment register prefetch pipeline (covers LDSM->QMMA latency)
//      + zero-C MMA partial init (no p-zeroing MOVs).
// ============================================================================

#define KDIM 7168
#define NDIM 256
#define KC 128
#define KB 56
#define MT 64
#define NTH 256
#define MMAX 16384

// ---- gemm shared memory layout (bytes) ----
#define OFF_BS 0            // [2][256][128] u8 = 65536 (swizzled)
#define OFF_AS 65536        // [2][64][128] u8 = 16384 (swizzled)
#define OFF_SC 81920        // [2][64] f32 = 512
#define OFF_WS 82432        // [112] f32 = 448
#define SMEM_TOTAL 82880

__device__ __align__(16) uint8_t g_w8[(size_t)NDIM * KDIM];
__device__ __align__(16) uint8_t g_x8[(size_t)MMAX * KDIM];
__device__ __align__(16) float g_scT[(size_t)KB * MMAX];

__device__ __forceinline__ uint32_t smem_u32(const void* p) {
    uint32_t a;
    asm("{ .reg .u64 t; cvta.to.shared.u64 t, %1; cvt.u32.u64 %0, t; }" : "=r"(a) : "l"(p));
    return a;
}

#define CP_ASYNC16(dst, src) \
    asm volatile("cp.async.cg.shared.global [%0], [%1], 16;" :: "r"(dst), "l"(src) : "memory")

#define LDMATRIX_X4(r0, r1, r2, r3, addr) \
    asm volatile("ldmatrix.sync.aligned.m8n8.x4.shared.b16 {%0,%1,%2,%3}, [%4];" \
        : "=r"(r0), "=r"(r1), "=r"(r2), "=r"(r3) : "r"(addr))

#define MMA_E4M3(d0, d1, d2, d3, a0, a1, a2, a3, b0, b1) \
    asm volatile("mma.sync.aligned.m16n8k32.row.col.f32.e4m3.e4m3.f32 " \
        "{%0,%1,%2,%3}, {%4,%5,%6,%7}, {%8,%9}, {%0,%1,%2,%3};" \
        : "+f"(d0), "+f"(d1), "+f"(d2), "+f"(d3) \
        : "r"(a0), "r"(a1), "r"(a2), "r"(a3), "r"(b0), "r"(b1))

#define MMA_E4M3_ZC(d0, d1, d2, d3, a0, a1, a2, a3, b0, b1, z) \
    asm volatile("mma.sync.aligned.m16n8k32.row.col.f32.e4m3.e4m3.f32 " \
        "{%0,%1,%2,%3}, {%4,%5,%6,%7}, {%8,%9}, {%10,%10,%10,%10};" \
        : "=f"(d0), "=f"(d1), "=f"(d2), "=f"(d3) \
        : "r"(a0), "r"(a1), "r"(a2), "r"(a3), "r"(b0), "r"(b1), "f"(z))

// ============================================================================
// Weight canonicalization (harness upcasts fp8 inputs to f32; detect + cvt).
// ============================================================================
__global__ void conv_kernel(const void* w) {
    __shared__ int cnt;
    const int tid = threadIdx.x;
    if (tid == 0) cnt = 0;
    __syncthreads();
    const float* wf = (const float*)w;
    int ok = 0;
#pragma unroll
    for (int i = 0; i < 16; ++i) {
        float v = wf[tid + i * 256];
        if (isfinite(v) && fabsf(v) <= 1.0f) ok++;
    }
#pragma unroll
    for (int o = 16; o; o >>= 1) ok += __shfl_xor_sync(0xffffffffu, ok, o);
    if ((tid & 31) == 0) atomicAdd(&cnt, ok);
    __syncthreads();
    const bool is_f32 = (cnt >= 4000);

    const int i4 = blockIdx.x * 256 + tid;
    constexpr int TOT4 = NDIM * KDIM / 4;
    if (i4 >= TOT4) return;
    uint32_t outw;
    if (is_f32) {
        const float4 v = ((const float4*)w)[i4];
        unsigned short lo, hi;
        asm("cvt.rn.satfinite.e4m3x2.f32 %0, %1, %2;" : "=h"(lo) : "f"(v.y), "f"(v.x));
        asm("cvt.rn.satfinite.e4m3x2.f32 %0, %1, %2;" : "=h"(hi) : "f"(v.w), "f"(v.z));
        outw = (uint32_t)lo | ((uint32_t)hi << 16);
    } else {
        outw = ((const uint32_t*)w)[i4];
    }
    ((uint32_t*)g_w8)[i4] = outw;
}

// ============================================================================
// Activation quantization: one CTA per row; warp w handles k-blocks w, w+8, ...
// Exact reference numerics (amax, RN divide, e4m3 RN-satfinite).
// ============================================================================
__global__ void __launch_bounds__(256, 4)
quant_kernel(const float* __restrict__ x, int M) {
    const int m = blockIdx.x;
    const int w = threadIdx.x >> 5;
    const int lane = threadIdx.x & 31;
    const float4* xr = (const float4*)(x + (size_t)m * KDIM);
    uint32_t* xq = (uint32_t*)(g_x8 + (size_t)m * KDIM);

    float4 v[7];
#pragma unroll
    for (int i = 0; i < 7; ++i) v[i] = xr[(w + i * 8) * 32 + lane];

    float am[7];
#pragma unroll
    for (int i = 0; i < 7; ++i)
        am[i] = fmaxf(fmaxf(fabsf(v[i].x), fabsf(v[i].y)),
                      fmaxf(fabsf(v[i].z), fabsf(v[i].w)));
#pragma unroll
    for (int o = 16; o; o >>= 1) {
#pragma unroll
        for (int i = 0; i < 7; ++i)
            am[i] = fmaxf(am[i], __shfl_xor_sync(0xffffffffu, am[i], o));
    }
#pragma unroll
    for (int i = 0; i < 7; ++i) {
        const int kb = w + i * 8;
        const float amax = fmaxf(am[i], 1e-8f);
        const float s = __fdiv_rn(amax, 448.0f);
        const float ri = __fdiv_rn(448.0f, amax);
        unsigned short lo, hi;
        asm("cvt.rn.satfinite.e4m3x2.f32 %0, %1, %2;"
            : "=h"(lo) : "f"(v[i].y * ri), "f"(v[i].x * ri));
        asm("cvt.rn.satfinite.e4m3x2.f32 %0, %1, %2;"
            : "=h"(hi) : "f"(v[i].w * ri), "f"(v[i].z * ri));
        xq[kb * 32 + lane] = (uint32_t)lo | ((uint32_t)hi << 16);
        if (lane == 0) g_scT[(size_t)kb * M + m] = s;
    }
}

// ============================================================================
// fp8 mma GEMM (A = pre-quantized activations, B = canonical fp8 weights)
// ============================================================================
__device__ __forceinline__ void issue_chunk(uint32_t sb, int tid, size_t m0cta,
                                            int kc, int st, int M) {
    // A tile: 64 rows x 128 fp8 (swizzled)
    {
        const int u = tid & 7;
        const int r0 = tid >> 3;
#pragma unroll
        for (int i = 0; i < 2; ++i) {
            const int row = r0 + i * 32;
            const uint32_t dst = sb + OFF_AS + st * 8192 + row * 128 + ((u ^ (row & 7)) * 16);
            const uint8_t* g = g_x8 + (m0cta + row) * KDIM + (size_t)kc * KC + u * 16;
            CP_ASYNC16(dst, g);
        }
    }
    // B tile: 256 rows x 128 fp8 (swizzled)
    {
        const int u = tid & 7;
        const int n0 = tid >> 3;
#pragma unroll
        for (int i = 0; i < 8; ++i) {
            const int n = n0 + i * 32;
            const uint32_t dst = sb + OFF_BS + st * 32768 + n * 128 + ((u ^ (n & 7)) * 16);
            const uint8_t* g = g_w8 + (size_t)n * KDIM + (size_t)kc * KC + u * 16;
            CP_ASYNC16(dst, g);
        }
    }
    // act scales: 64 contiguous f32 from transposed table
    if (tid < 16) {
        const uint32_t dst = sb + OFF_SC + st * 256 + tid * 16;
        const float* g = g_scT + (size_t)kc * M + m0cta + tid * 4;
        CP_ASYNC16(dst, g);
    }
    asm volatile("cp.async.commit_group;" ::: "memory");
}

__global__ void __launch_bounds__(NTH, 2)
fused_fp8_gemm(const float* __restrict__ ws, float* __restrict__ out, int M) {
    extern __shared__ char smem[];
    const uint32_t sb = smem_u32(smem);
    const int tid = threadIdx.x;
    const int lane = tid & 31;
    const int wid = tid >> 5;
    const size_t m0cta = (size_t)blockIdx.x * MT;

    if (tid < 112) ((float*)(smem + OFF_WS))[tid] = ws[tid];

    // warp grid 2m x 4n, warp tile m32 x n64
    const int R0 = (wid >> 2) * 32;
    const int C0 = (wid & 3) * 64;
    const int nb = (wid & 3) >> 1;
    const int alane = lane & 15, asel = lane >> 4;
    const int nlane = (lane & 7) | ((lane >> 4) << 3);
    const int bsel = (lane >> 3) & 1;
    const int lr = lane >> 2;

    float acc[64];
#pragma unroll
    for (int i = 0; i < 64; ++i) acc[i] = 0.f;

    issue_chunk(sb, tid, m0cta, 0, 0, M);
    issue_chunk(sb, tid, m0cta, 1, 1, M);

    const float* SC = (const float*)(smem + OFF_SC);
    const float* WS = (const float*)(smem + OFF_WS);

#pragma unroll 1
    for (int kc = 0; kc < KB; ++kc) {
        const int st = kc & 1;
        if (kc == KB - 1) { asm volatile("cp.async.wait_group 0;" ::: "memory"); }
        else              { asm volatile("cp.async.wait_group 1;" ::: "memory"); }
        __syncthreads();

        const uint32_t ab = sb + OFF_AS + st * 8192;
        const uint32_t bb = sb + OFF_BS + st * 32768;
        const float wv = WS[nb * 56 + kc];
        float f[4];
#pragma unroll
        for (int mh = 0; mh < 2; ++mh) {
            f[mh * 2 + 0] = SC[st * 64 + R0 + mh * 16 + lr] * wv;
            f[mh * 2 + 1] = SC[st * 64 + R0 + mh * 16 + 8 + lr] * wv;
        }

        // B-fragment double buffer; step s = kh*8 + ng*2 + ks2 (16 steps)
        uint32_t bf[2][4];
        // prime: step 0 fragment (ng=0, ks=0)
        {
            const int nr = C0 + nlane;
            const uint32_t bd = bb + nr * 128 + ((bsel ^ (nr & 7)) * 16);
            LDMATRIX_X4(bf[0][0], bf[0][1], bf[0][2], bf[0][3], bd);
        }

#pragma unroll
        for (int kh = 0; kh < 2; ++kh) {
            // preload A fragments for this k-half (2 ks2 x 2 mh)
            uint32_t a[2][2][4];
#pragma unroll
            for (int ks2 = 0; ks2 < 2; ++ks2) {
#pragma unroll
                for (int mh = 0; mh < 2; ++mh) {
                    const int r = R0 + mh * 16 + alane;
                    const int ks = kh * 2 + ks2;
                    const uint32_t ad = ab + r * 128 + (((ks * 2 + asel) ^ (r & 7)) * 16);
                    LDMATRIX_X4(a[ks2][mh][0], a[ks2][mh][1], a[ks2][mh][2], a[ks2][mh][3], ad);
                }
            }

#pragma unroll
            for (int ng = 0; ng < 4; ++ng) {
                float p[16];
#pragma unroll
                for (int ks2 = 0; ks2 < 2; ++ks2) {
                    const int s = kh * 8 + ng * 2 + ks2;       // compile-time
                    const int buf = s & 1;
                    // prefetch next step's B fragment into the other buffer
                    if (s < 15) {
                        const int sn = s + 1;
                        const int n_ng = (sn >> 1) & 3;
                        const int n_ks = ((sn >> 3) << 1) | (sn & 1);
                        const int nr = C0 + n_ng * 16 + nlane;
                        const uint32_t bd = bb + nr * 128 + (((n_ks * 2 + bsel) ^ (nr & 7)) * 16);
                        LDMATRIX_X4(bf[buf ^ 1][0], bf[buf ^ 1][1], bf[buf ^ 1][2], bf[buf ^ 1][3], bd);
                    }
                    if (ks2 == 0) {
#pragma unroll
                        for (int mh = 0; mh < 2; ++mh) {
                            MMA_E4M3_ZC(p[mh*8+0], p[mh*8+1], p[mh*8+2], p[mh*8+3],
                                        a[0][mh][0], a[0][mh][1], a[0][mh][2], a[0][mh][3],
                                        bf[buf][0], bf[buf][1], 0.f);
                            MMA_E4M3_ZC(p[mh*8+4], p[mh*8+5], p[mh*8+6], p[mh*8+7],
                                        a[0][mh][0], a[0][mh][1], a[0][mh][2], a[0][mh][3],
                                        bf[buf][2], bf[buf][3], 0.f);
                        }
                    } else {
#pragma unroll
                        for (int mh = 0; mh < 2; ++mh) {
                            MMA_E4M3(p[mh*8+0], p[mh*8+1], p[mh*8+2], p[mh*8+3],
                                     a[1][mh][0], a[1][mh][1], a[1][mh][2], a[1][mh][3],
                                     bf[buf][0], bf[buf][1]);
                            MMA_E4M3(p[mh*8+4], p[mh*8+5], p[mh*8+6], p[mh*8+7],
                                     a[1][mh][0], a[1][mh][1], a[1][mh][2], a[1][mh][3],
                                     bf[buf][2], bf[buf][3]);
                        }
                    }
                }
                // fold per-block scales into fp32 accumulator (per k-half)
#pragma unroll
                for (int mh = 0; mh < 2; ++mh) {
#pragma unroll
                    for (int pr = 0; pr < 2; ++pr) {
                        const int pi = mh * 8 + pr * 4;
                        const int ai = ng * 16 + pi;
                        acc[ai+0] = fmaf(p[pi+0], f[mh*2+0], acc[ai+0]);
                        acc[ai+1] = fmaf(p[pi+1], f[mh*2+0], acc[ai+1]);
                        acc[ai+2] = fmaf(p[pi+2], f[mh*2+1], acc[ai+2]);
                        acc[ai+3] = fmaf(p[pi+3], f[mh*2+1], acc[ai+3]);
                    }
                }
            }
        }
        __syncthreads();
        if (kc + 2 < KB) issue_chunk(sb, tid, m0cta, kc + 2, st, M);
    }

    // ================= epilogue =================
#pragma unroll
    for (int mh = 0; mh < 2; ++mh) {
        const int row = R0 + mh * 16 + lr;
        float* o0 = out + (m0cta + row) * NDIM;
#pragma unroll
        for (int ng = 0; ng < 4; ++ng) {
#pragma unroll
            for (int pr = 0; pr < 2; ++pr) {
                const int base = ng * 16 + mh * 8 + pr * 4;
                const int col = C0 + ng * 16 + pr * 8 + (lane & 3) * 2;
                *(float2*)(o0 + col) = make_float2(acc[base], acc[base+1]);
                *(float2*)(o0 + 8 * NDIM + col) = make_float2(acc[base+2], acc[base+3]);
            }
        }
    }
}

// ============================================================================
extern "C" void kernel_launch(void* const* d_in, const int* in_sizes, int n_in,
                              void* d_out, int out_size) {
    const float* x = (const float*)d_in[0];
    const void* w = d_in[1];
    const float* ws = (const float*)d_in[2];
    float* out = (float*)d_out;

    const int M = in_sizes[0] / KDIM;       // 16384
    const int grid = M / MT;                // 256

    cudaFuncSetAttribute(fused_fp8_gemm, cudaFuncAttributeMaxDynamicSharedMemorySize, SMEM_TOTAL);

    conv_kernel<<<(NDIM * KDIM / 4 + 255) / 256, 256>>>(w);
    quant_kernel<<<M, 256>>>(x, M);
    fused_fp8_gemm<<<grid, NTH, SMEM_TOTAL>>>(ws, out, M);
}